// round 16
// baseline (speedup 1.0000x reference)
#include <cuda_runtime.h>
#include <math.h>
#include <string.h>

#define PP    33
#define IMG   256
#define NT    1024
#define NPAIR (PP * 17)          // 561

// ==================== compile-time T tables ====================
struct alignas(16) Tables {
    float ts [PP][18][2];   // Ts17[i][a], a<=16 (row-uniform stage-1 reads), padded
    float tta[9][36][4];    // (T[j][2g].re, .re, .im, .im)   lane reads, stage 2
    float ttb[9][36][4];    // (T[j][2g+1].re, .re, .im, .im)
    float ttc[36][2];       // T[j][16] (== 479, kept as table)
};

constexpr double CPI = 3.14159265358979323846;

constexpr double csin(double x) {
    double t = x, s = x;
    for (int i = 1; i <= 15; i++) { t *= -(x * x) / double((2 * i) * (2 * i + 1)); s += t; }
    return s;
}
constexpr double ccos(double x) {
    double t = 1.0, s = 1.0;
    for (int i = 1; i <= 15; i++) { t *= -(x * x) / double((2 * i - 1) * (2 * i)); s += t; }
    return s;
}

constexpr Tables make_tables() {
    Tables tb{};
    for (int q = 0; q < PP; q++) {
        int ii  = (q + 16) % PP;           // undo ifftshift
        int n16 = 478 * ii;                // c = ii*478/32 exactly
        int n   = n16 / 32;
        double f = (double)(n16 % 32) / 32.0;
        for (int rp = 0; rp <= 16; rp++) {
            int neg2as = 2 * (16 - rp);
            int m1 = (neg2as * (n + 1)) % 958; if (m1 > 479) m1 -= 958;
            int m2 = (neg2as * (n + 2)) % 958; if (m2 > 479) m2 -= 958;
            double a1 = CPI * (double)m1 / 479.0;
            double a2 = CPI * (double)m2 / 479.0;
            double w0 = 479.0 * (1.0 - f), w1 = 479.0 * f;
            double tre = w0 * ccos(a1) + w1 * ccos(a2);
            double tim = w0 * csin(a1) + w1 * csin(a2);
            tb.ts[q][rp][0] = (float)tre;
            tb.ts[q][rp][1] = (float)tim;
            if (rp < 16) {
                int g = rp >> 1;
                if ((rp & 1) == 0) {
                    tb.tta[g][q][0] = (float)tre; tb.tta[g][q][1] = (float)tre;
                    tb.tta[g][q][2] = (float)tim; tb.tta[g][q][3] = (float)tim;
                } else {
                    tb.ttb[g][q][0] = (float)tre; tb.ttb[g][q][1] = (float)tre;
                    tb.ttb[g][q][2] = (float)tim; tb.ttb[g][q][3] = (float)tim;
                }
            } else {
                tb.ttc[q][0] = (float)tre; tb.ttc[q][1] = (float)tim;
            }
        }
    }
    return tb;
}

__device__ const Tables g_tab = make_tables();

static_assert(sizeof(Tables) % 16 == 0, "16B multiple");
#define TAB_F4 (sizeof(Tables) / 16)      // 963

// packed dual-FMA: (a.x*b.x+c.x, a.y*b.y+c.y) in ONE instruction
__device__ __forceinline__ float2 f2fma(float2 a, float2 b, float2 c) {
    unsigned long long ua, ub, uc, ud;
    memcpy(&ua, &a, 8); memcpy(&ub, &b, 8); memcpy(&uc, &c, 8);
    asm("fma.rn.f32x2 %0, %1, %2, %3;" : "=l"(ud) : "l"(ua), "l"(ub), "l"(uc));
    float2 d; memcpy(&d, &ud, 8); return d;
}

__device__ __forceinline__ float2 warp_reduce_c(float2 p) {
#pragma unroll
    for (int off = 16; off; off >>= 1) {
        p.x += __shfl_xor_sync(0xffffffffu, p.x, off);
        p.y += __shfl_xor_sync(0xffffffffu, p.y, off);
    }
    return p;
}

__global__ __launch_bounds__(NT, 1)
void taper_kernel(const float* __restrict__ ref,
                  const float* __restrict__ mov,
                  const int* __restrict__ xp,
                  const int* __restrict__ yp,
                  float* __restrict__ out, int B) {
    __shared__ Tables s_tab;
    __shared__ float2 PSD[17][36];         // (p[a]+p[32-a], p[a]-p[32-a]); PSD[16]=(p16,0)
    __shared__ float2 Vw[32][34];
    __shared__ float4 SDs[32][16];         // (s.x, s.y, -d.y, d.x)

    int ib = blockIdx.x;
    const float* img;
    float2* o;
    if (ib < B) {
        img = ref + (size_t)ib * IMG * IMG;
        o   = (float2*)out + (size_t)ib * PP * PP;
    } else {
        img = mov + (size_t)(ib - B) * IMG * IMG;
        o   = (float2*)out + (size_t)B * PP * PP + (size_t)(ib - B) * PP * PP;
    }

    int tid  = threadIdx.x;
    int w    = tid >> 5;
    int lane = tid & 31;

    int x0 = xp ? __ldg(xp) : 100;
    int y0 = yp ? __ldg(yp) : 50;

    // ---- Phase A: table copy (coalesced) + patch pairs (speculative at (100,50))
    if (tid < TAB_F4) {
        reinterpret_cast<float4*>(&s_tab)[tid] =
            reinterpret_cast<const float4*>(&g_tab)[tid];
    }
    if (tid >= 463) {
        int ip = tid - 463;                // 0..560
        int qp = ip / PP;
        int r  = ip - qp * PP;
        float pa = img[(size_t)(100 + qp) * IMG + (50 + r)];
        float pm = img[(size_t)(132 - qp) * IMG + (50 + r)];
        if (x0 != 100 || y0 != 50) {       // correctness net; never taken in practice
            pa = img[(size_t)(x0 + qp) * IMG + (y0 + r)];
            pm = img[(size_t)(x0 + 32 - qp) * IMG + (y0 + r)];
        }
        PSD[qp][r] = (qp == 16) ? make_float2(pa, 0.0f)
                                : make_float2(pa + pm, pa - pm);
    }
    __syncthreads();                       // the ONLY block-wide barrier

    // ---- Stage 1 (row w) + folded V32 row, all in packed f32x2
    const float4* trow = reinterpret_cast<const float4*>(s_tab.ts[w]);   // uniform
    const float4* tr32 = reinterpret_cast<const float4*>(s_tab.ts[32]);  // uniform
    float2 v  = make_float2(0.f, 0.f), v2 = v;   // V[w][lane]
    float2 wv = v;                                // V[w][32]
    float2 u  = v, u2 = v;                        // V32[lane]
    float2 cv = v;                                // V32[32]
#pragma unroll
    for (int h = 0; h < 8; h++) {
        float4 tv = trow[h];
        float4 t3 = tr32[h];
        float2 tvlo = make_float2(tv.x, tv.y), tvhi = make_float2(tv.z, tv.w);
        float2 t3lo = make_float2(t3.x, t3.y), t3hi = make_float2(t3.z, t3.w);
        float2 p0 = PSD[2 * h][lane], p1 = PSD[2 * h + 1][lane];
        float2 q0 = PSD[2 * h][32],   q1 = PSD[2 * h + 1][32];       // uniform
        v  = f2fma(tvlo, p0, v);
        v2 = f2fma(tvhi, p1, v2);
        wv = f2fma(tvlo, q0, wv);  wv = f2fma(tvhi, q1, wv);
        u  = f2fma(t3lo, p0, u);
        u2 = f2fma(t3hi, p1, u2);
        cv = f2fma(t3lo, q0, cv);  cv = f2fma(t3hi, q1, cv);
    }
    float tlw  = s_tab.ts[w][16][0];       // == 479 (real)
    float tl32 = s_tab.ts[32][16][0];
    float p16l = PSD[16][lane].x;
    float p16c = PSD[16][32].x;            // uniform
    float2 Vlane = make_float2(fmaf(tlw,  p16l, v.x + v2.x), v.y + v2.y);
    float2 V32l  = make_float2(fmaf(tl32, p16l, u.x + u2.x), u.y + u2.y);
    float2 V32c  = make_float2(fmaf(tl32, p16c, cv.x), cv.y);
    float2 Vc32  = make_float2(fmaf(tlw,  p16c, wv.x), wv.y);

    Vw[w][lane] = Vlane;
    if (lane == 0) Vw[w][32] = Vc32;
    __syncwarp();
    if (lane < 16) {
        float2 vb = Vw[w][lane];
        float2 vm = Vw[w][32 - lane];
        SDs[w][lane] = make_float4(vb.x + vm.x, vb.y + vm.y,
                                   -(vb.y - vm.y), vb.x - vm.x);
    }
    __syncwarp();

    // ---- Stage 2 main: out[w][lane], packed (4 FFMA2 / iter)
    float2 acc = make_float2(0.f, 0.f), acc2 = acc;
#pragma unroll
    for (int g = 0; g < 8; g++) {
        float4 ta  = reinterpret_cast<const float4*>(s_tab.tta[g])[lane];
        float4 tb2 = reinterpret_cast<const float4*>(s_tab.ttb[g])[lane];
        float4 sd0 = SDs[w][2 * g];                    // uniform
        float4 sd1 = SDs[w][2 * g + 1];
        acc  = f2fma(make_float2(ta.x,  ta.y),  make_float2(sd0.x, sd0.y), acc);
        acc  = f2fma(make_float2(ta.z,  ta.w),  make_float2(sd0.z, sd0.w), acc);
        acc2 = f2fma(make_float2(tb2.x, tb2.y), make_float2(sd1.x, sd1.y), acc2);
        acc2 = f2fma(make_float2(tb2.z, tb2.w), make_float2(sd1.z, sd1.w), acc2);
    }
    float2 vc = Vw[w][16];                             // uniform
    float  tc = s_tab.ttc[lane][0];                    // == 479 (real)
    float2* orow = o + (size_t)w * PP;
    orow[lane] = make_float2(fmaf(vc.x, tc, acc.x + acc2.x),
                             fmaf(vc.y, tc, acc.y + acc2.y));

    // lane-varying T reads via conjugate fold
    int   sel = (lane <= 16) ? lane : 32 - lane;
    float sgn = (lane <= 16) ? 1.0f : -1.0f;

    // ---- out[w][32] = sum_b V[w][b] * T[32][b]
    {
        float2 t = make_float2(s_tab.ts[32][sel][0], s_tab.ts[32][sel][1] * sgn);
        float2 p = make_float2(fmaf(Vlane.x, t.x, -Vlane.y * t.y),
                               fmaf(Vlane.x, t.y,  Vlane.y * t.x));
        if (lane == 0) {                               // b = 32: T[32][32] = conj(T[32][0])
            float2 t32 = make_float2(s_tab.ts[32][0][0], -s_tab.ts[32][0][1]);
            p.x += Vc32.x * t32.x - Vc32.y * t32.y;
            p.y += Vc32.x * t32.y + Vc32.y * t32.x;
        }
        p = warp_reduce_c(p);
        if (lane == 0) orow[32] = p;
    }

    // ---- out[32][w] = sum_b V32[b] * T[w][b]
    {
        float2 t = make_float2(s_tab.ts[w][sel][0], s_tab.ts[w][sel][1] * sgn);
        float2 p = make_float2(fmaf(V32l.x, t.x, -V32l.y * t.y),
                               fmaf(V32l.x, t.y,  V32l.y * t.x));
        if (lane == 0) {                               // b = 32: T[w][32] = conj(T[w][0])
            float2 tw = make_float2(s_tab.ts[w][0][0], -s_tab.ts[w][0][1]);
            p.x += V32c.x * tw.x - V32c.y * tw.y;
            p.y += V32c.x * tw.y + V32c.y * tw.x;
        }
        p = warp_reduce_c(p);
        if (lane == 0) o[(size_t)32 * PP + w] = p;
    }

    // ---- corner out[32][32] (warp 31 only)
    if (w == 31) {
        float2 t = make_float2(s_tab.ts[32][sel][0], s_tab.ts[32][sel][1] * sgn);
        float2 p = make_float2(fmaf(V32l.x, t.x, -V32l.y * t.y),
                               fmaf(V32l.x, t.y,  V32l.y * t.x));
        if (lane == 0) {
            float2 t32 = make_float2(s_tab.ts[32][0][0], -s_tab.ts[32][0][1]);
            p.x += V32c.x * t32.x - V32c.y * t32.y;
            p.y += V32c.x * t32.y + V32c.y * t32.x;
        }
        p = warp_reduce_c(p);
        if (lane == 0) o[(size_t)32 * PP + 32] = p;
    }
}

extern "C" void kernel_launch(void* const* d_in, const int* in_sizes, int n_in,
                              void* d_out, int out_size) {
    const float* ref = (const float*)d_in[0];
    const float* mov = (const float*)d_in[1];
    const int* xp = (n_in > 2) ? (const int*)d_in[2] : nullptr;
    const int* yp = (n_in > 3) ? (const int*)d_in[3] : nullptr;
    float* out = (float*)d_out;
    int B = in_sizes[0] / (IMG * IMG);

    taper_kernel<<<2 * B, NT>>>(ref, mov, xp, yp, out, B);
}

// round 17
// speedup vs baseline: 1.0238x; 1.0238x over previous
#include <cuda_runtime.h>
#include <math.h>
#include <string.h>

#define PP    33
#define IMG   256
#define NT    1024
#define NPAIR (PP * 17)          // 561

// ==================== compile-time T tables (exact, double precision) ====================
struct alignas(16) Tables {
    float ts [PP][18][2];   // T[i][a], a<=16 (row-uniform stage-1 reads), padded
    float tta[9][36][4];    // (T[j][2g].re, .re, .im, .im)   lane reads, stage 2
    float ttb[9][36][4];    // (T[j][2g+1].re, .re, .im, .im)
    float ttc[36][2];       // T[j][16]
};

constexpr double CPI = 3.14159265358979323846;

constexpr double csin(double x) {
    double t = x, s = x;
    for (int i = 1; i <= 15; i++) { t *= -(x * x) / double((2 * i) * (2 * i + 1)); s += t; }
    return s;
}
constexpr double ccos(double x) {
    double t = 1.0, s = 1.0;
    for (int i = 1; i <= 15; i++) { t *= -(x * x) / double((2 * i - 1) * (2 * i)); s += t; }
    return s;
}

constexpr Tables make_tables() {
    Tables tb{};
    for (int q = 0; q < PP; q++) {
        int ii  = (q + 16) % PP;           // undo ifftshift
        int n16 = 478 * ii;                // c = ii*478/32 exactly
        int n   = n16 / 32;
        double f = (double)(n16 % 32) / 32.0;
        for (int rp = 0; rp <= 16; rp++) {
            int neg2as = 2 * (16 - rp);
            int m1 = (neg2as * (n + 1)) % 958; if (m1 > 479) m1 -= 958;
            int m2 = (neg2as * (n + 2)) % 958; if (m2 > 479) m2 -= 958;
            double a1 = CPI * (double)m1 / 479.0;
            double a2 = CPI * (double)m2 / 479.0;
            double w0 = 479.0 * (1.0 - f), w1 = 479.0 * f;
            double tre = w0 * ccos(a1) + w1 * ccos(a2);
            double tim = w0 * csin(a1) + w1 * csin(a2);
            tb.ts[q][rp][0] = (float)tre;
            tb.ts[q][rp][1] = (float)tim;
            if (rp < 16) {
                int g = rp >> 1;
                if ((rp & 1) == 0) {
                    tb.tta[g][q][0] = (float)tre; tb.tta[g][q][1] = (float)tre;
                    tb.tta[g][q][2] = (float)tim; tb.tta[g][q][3] = (float)tim;
                } else {
                    tb.ttb[g][q][0] = (float)tre; tb.ttb[g][q][1] = (float)tre;
                    tb.ttb[g][q][2] = (float)tim; tb.ttb[g][q][3] = (float)tim;
                }
            } else {
                tb.ttc[q][0] = (float)tre; tb.ttc[q][1] = (float)tim;
            }
        }
    }
    return tb;
}

__device__ const Tables g_tab = make_tables();

// packed dual-FMA: (a.x*b.x+c.x, a.y*b.y+c.y) in ONE instruction
__device__ __forceinline__ float2 f2fma(float2 a, float2 b, float2 c) {
    unsigned long long ua, ub, uc, ud;
    memcpy(&ua, &a, 8); memcpy(&ub, &b, 8); memcpy(&uc, &c, 8);
    asm("fma.rn.f32x2 %0, %1, %2, %3;" : "=l"(ud) : "l"(ua), "l"(ub), "l"(uc));
    float2 d; memcpy(&d, &ud, 8); return d;
}

__device__ __forceinline__ float2 warp_reduce_c(float2 p) {
#pragma unroll
    for (int off = 16; off; off >>= 1) {
        p.x += __shfl_xor_sync(0xffffffffu, p.x, off);
        p.y += __shfl_xor_sync(0xffffffffu, p.y, off);
    }
    return p;
}

__global__ __launch_bounds__(NT, 1)
void taper_kernel(const float* __restrict__ ref,
                  const float* __restrict__ mov,
                  const int* __restrict__ xp,
                  const int* __restrict__ yp,
                  float* __restrict__ out, int B) {
    __shared__ float2 PSD[17][36];         // (p[a]+p[32-a], p[a]-p[32-a]); PSD[16]=(p16,0)
    __shared__ float2 Vw[32][34];
    __shared__ float4 SDs[32][16];         // (s.x, s.y, -d.y, d.x)

    int ib = blockIdx.x;
    const float* img;
    float2* o;
    if (ib < B) {
        img = ref + (size_t)ib * IMG * IMG;
        o   = (float2*)out + (size_t)ib * PP * PP;
    } else {
        img = mov + (size_t)(ib - B) * IMG * IMG;
        o   = (float2*)out + (size_t)B * PP * PP + (size_t)(ib - B) * PP * PP;
    }

    int tid  = threadIdx.x;
    int w    = tid >> 5;
    int lane = tid & 31;

    int x0 = xp ? __ldg(xp) : 100;
    int y0 = yp ? __ldg(yp) : 50;

    // ---- Phase A: ONLY the patch pairs go through smem (speculative at (100,50)).
    if (tid >= 463) {
        int ip = tid - 463;                // 0..560
        int qp = ip / PP;
        int r  = ip - qp * PP;
        float pa = img[(size_t)(100 + qp) * IMG + (50 + r)];
        float pm = img[(size_t)(132 - qp) * IMG + (50 + r)];
        if (x0 != 100 || y0 != 50) {       // correctness net; never taken in practice
            pa = img[(size_t)(x0 + qp) * IMG + (y0 + r)];
            pm = img[(size_t)(x0 + 32 - qp) * IMG + (y0 + r)];
        }
        PSD[qp][r] = (qp == 16) ? make_float2(pa, 0.0f)
                                : make_float2(pa + pm, pa - pm);
    }
    __syncthreads();                       // the ONLY block-wide barrier

    // ---- Stage 1 (row w) + folded V32 row; T read straight from gmem (L1/L2 cached)
    const float4* trow = reinterpret_cast<const float4*>(g_tab.ts[w]);   // warp-uniform
    const float4* tr32 = reinterpret_cast<const float4*>(g_tab.ts[32]);  // uniform
    float2 v  = make_float2(0.f, 0.f), v2 = v;   // V[w][lane]
    float2 wv = v;                                // V[w][32]
    float2 u  = v, u2 = v;                        // V32[lane]
    float2 cv = v;                                // V32[32]
#pragma unroll
    for (int h = 0; h < 8; h++) {
        float4 tv = __ldg(&trow[h]);
        float4 t3 = __ldg(&tr32[h]);
        float2 tvlo = make_float2(tv.x, tv.y), tvhi = make_float2(tv.z, tv.w);
        float2 t3lo = make_float2(t3.x, t3.y), t3hi = make_float2(t3.z, t3.w);
        float2 p0 = PSD[2 * h][lane], p1 = PSD[2 * h + 1][lane];
        float2 q0 = PSD[2 * h][32],   q1 = PSD[2 * h + 1][32];       // uniform
        v  = f2fma(tvlo, p0, v);
        v2 = f2fma(tvhi, p1, v2);
        wv = f2fma(tvlo, q0, wv);  wv = f2fma(tvhi, q1, wv);
        u  = f2fma(t3lo, p0, u);
        u2 = f2fma(t3hi, p1, u2);
        cv = f2fma(t3lo, q0, cv);  cv = f2fma(t3hi, q1, cv);
    }
    float tlw  = __ldg(&g_tab.ts[w][16][0]);       // == 479 (real)
    float tl32 = __ldg(&g_tab.ts[32][16][0]);
    float p16l = PSD[16][lane].x;
    float p16c = PSD[16][32].x;                    // uniform
    float2 Vlane = make_float2(fmaf(tlw,  p16l, v.x + v2.x), v.y + v2.y);
    float2 V32l  = make_float2(fmaf(tl32, p16l, u.x + u2.x), u.y + u2.y);
    float2 V32c  = make_float2(fmaf(tl32, p16c, cv.x), cv.y);
    float2 Vc32  = make_float2(fmaf(tlw,  p16c, wv.x), wv.y);

    Vw[w][lane] = Vlane;
    if (lane == 0) Vw[w][32] = Vc32;
    __syncwarp();
    if (lane < 16) {
        float2 vb = Vw[w][lane];
        float2 vm = Vw[w][32 - lane];
        SDs[w][lane] = make_float4(vb.x + vm.x, vb.y + vm.y,
                                   -(vb.y - vm.y), vb.x - vm.x);
    }
    __syncwarp();

    // ---- Stage 2 main: out[w][lane], packed (4 FFMA2 / iter), T coalesced from gmem
    float2 acc = make_float2(0.f, 0.f), acc2 = acc;
#pragma unroll
    for (int g = 0; g < 8; g++) {
        float4 ta  = __ldg(&reinterpret_cast<const float4*>(g_tab.tta[g])[lane]);
        float4 tb2 = __ldg(&reinterpret_cast<const float4*>(g_tab.ttb[g])[lane]);
        float4 sd0 = SDs[w][2 * g];                    // uniform
        float4 sd1 = SDs[w][2 * g + 1];
        acc  = f2fma(make_float2(ta.x,  ta.y),  make_float2(sd0.x, sd0.y), acc);
        acc  = f2fma(make_float2(ta.z,  ta.w),  make_float2(sd0.z, sd0.w), acc);
        acc2 = f2fma(make_float2(tb2.x, tb2.y), make_float2(sd1.x, sd1.y), acc2);
        acc2 = f2fma(make_float2(tb2.z, tb2.w), make_float2(sd1.z, sd1.w), acc2);
    }
    float2 vc = Vw[w][16];                             // uniform
    float  tc = __ldg(&g_tab.ttc[lane][0]);            // == 479 (real)
    float2* orow = o + (size_t)w * PP;
    orow[lane] = make_float2(fmaf(vc.x, tc, acc.x + acc2.x),
                             fmaf(vc.y, tc, acc.y + acc2.y));

    // lane-varying T reads via conjugate fold
    int   sel = (lane <= 16) ? lane : 32 - lane;
    float sgn = (lane <= 16) ? 1.0f : -1.0f;

    // ---- out[w][32] = sum_b V[w][b] * T[32][b]
    {
        float2 t = make_float2(__ldg(&g_tab.ts[32][sel][0]),
                               __ldg(&g_tab.ts[32][sel][1]) * sgn);
        float2 p = make_float2(fmaf(Vlane.x, t.x, -Vlane.y * t.y),
                               fmaf(Vlane.x, t.y,  Vlane.y * t.x));
        if (lane == 0) {                               // b = 32: T[32][32] = conj(T[32][0])
            float2 t32 = make_float2(__ldg(&g_tab.ts[32][0][0]),
                                     -__ldg(&g_tab.ts[32][0][1]));
            p.x += Vc32.x * t32.x - Vc32.y * t32.y;
            p.y += Vc32.x * t32.y + Vc32.y * t32.x;
        }
        p = warp_reduce_c(p);
        if (lane == 0) orow[32] = p;
    }

    // ---- out[32][w] = sum_b V32[b] * T[w][b]
    {
        float2 t = make_float2(__ldg(&g_tab.ts[w][sel][0]),
                               __ldg(&g_tab.ts[w][sel][1]) * sgn);
        float2 p = make_float2(fmaf(V32l.x, t.x, -V32l.y * t.y),
                               fmaf(V32l.x, t.y,  V32l.y * t.x));
        if (lane == 0) {                               // b = 32: T[w][32] = conj(T[w][0])
            float2 tw = make_float2(__ldg(&g_tab.ts[w][0][0]),
                                    -__ldg(&g_tab.ts[w][0][1]));
            p.x += V32c.x * tw.x - V32c.y * tw.y;
            p.y += V32c.x * tw.y + V32c.y * tw.x;
        }
        p = warp_reduce_c(p);
        if (lane == 0) o[(size_t)32 * PP + w] = p;
    }

    // ---- corner out[32][32] (warp 31 only)
    if (w == 31) {
        float2 t = make_float2(__ldg(&g_tab.ts[32][sel][0]),
                               __ldg(&g_tab.ts[32][sel][1]) * sgn);
        float2 p = make_float2(fmaf(V32l.x, t.x, -V32l.y * t.y),
                               fmaf(V32l.x, t.y,  V32l.y * t.x));
        if (lane == 0) {
            float2 t32 = make_float2(__ldg(&g_tab.ts[32][0][0]),
                                     -__ldg(&g_tab.ts[32][0][1]));
            p.x += V32c.x * t32.x - V32c.y * t32.y;
            p.y += V32c.x * t32.y + V32c.y * t32.x;
        }
        p = warp_reduce_c(p);
        if (lane == 0) o[(size_t)32 * PP + 32] = p;
    }
}

extern "C" void kernel_launch(void* const* d_in, const int* in_sizes, int n_in,
                              void* d_out, int out_size) {
    const float* ref = (const float*)d_in[0];
    const float* mov = (const float*)d_in[1];
    const int* xp = (n_in > 2) ? (const int*)d_in[2] : nullptr;
    const int* yp = (n_in > 3) ? (const int*)d_in[3] : nullptr;
    float* out = (float*)d_out;
    int B = in_sizes[0] / (IMG * IMG);

    taper_kernel<<<2 * B, NT>>>(ref, mov, xp, yp, out, B);
}